// round 11
// baseline (speedup 1.0000x reference)
#include <cuda_runtime.h>
#include <cstdint>

#define KC       32
#define DD       64
#define CPAD     36            // padded row stride (floats): conflict-free LDS.128
#define MAX_M    1500          // rows held in SMEM
#define ITERS    50
#define TAU      2e-5f
// s = (1/eps)*log2(e) = 10 * 1.4426950408889634
#define SLOG2    14.426950408889634f
#define S2LOG2   28.853900817779268f
#define NEGBIG   -1.0e30f

#define NTH2     1024          // phase-B threads
#define NW2      32            // phase-B warps

// Scratch: (400000 samples + 512*8 pad) * 32 cols = 12,931,072 floats.
__device__ float g_cscratch[13100000u];

__device__ __forceinline__ float ex2f(float x) {
    float y; asm("ex2.approx.ftz.f32 %0, %1;" : "=f"(y) : "f"(x)); return y;
}
__device__ __forceinline__ float rcpf(float x) {
    float y; asm("rcp.approx.ftz.f32 %0, %1;" : "=f"(y) : "f"(x)); return y;
}
__device__ __forceinline__ float warpAllSum(float v) {
#pragma unroll
    for (int off = 16; off; off >>= 1) v += __shfl_xor_sync(0xffffffffu, v, off);
    return v;
}
__device__ __forceinline__ float warpAllMax(float v) {
#pragma unroll
    for (int off = 16; off; off >>= 1) v = fmaxf(v, __shfl_xor_sync(0xffffffffu, v, off));
    return v;
}
__device__ __forceinline__ int lower_bound_dev(const int* __restrict__ a, int n, int key) {
    int lo = 0, hi = n;
    while (lo < hi) { int mid = (lo + hi) >> 1; if (__ldg(a + mid) < key) lo = mid + 1; else hi = mid; }
    return lo;
}

// =============== Kernel 1: cost rows (Phase A), all samples ===============
// row(i) = s*(v - vmax), v_j = 2s*(x_i . cb_j) - s*||cb_j||^2; per-row vmax
// shift makes max_j = 0 (||x||^2 and clamp cancel in all softmax/LSE).
// Destination row = i + 8*graph(i); 8 pad rows per graph filled with NEGBIG.
extern "C" __global__ void phaseA_kernel(const float* __restrict__ X,
                                         const float* __restrict__ cb,
                                         const int* __restrict__ bidx,
                                         int N, int S, int Mtot, int B) {
    __shared__ float cbS[KC * DD];
    __shared__ float sB[KC];
    const int tid = threadIdx.x;
    for (int i = tid; i < KC * DD; i += blockDim.x) cbS[i] = __ldg(cb + i);
    if (tid < KC) {
        float s = 0.f;
#pragma unroll
        for (int d = 0; d < DD; d++) { float v = __ldg(cb + tid * DD + d); s = fmaf(v, v, s); }
        sB[tid] = SLOG2 * s;
    }
    __syncthreads();

    int i = blockIdx.x * blockDim.x + tid;
    if (i < Mtot) {
        int node = i / S;
        int b = __ldg(bidx + node);
        float* dst = g_cscratch + ((size_t)i + (size_t)b * 8) * KC;

        const float4* xr = (const float4*)(X + (size_t)i * DD);
        float4 x4[16];
#pragma unroll
        for (int q = 0; q < 16; q++) x4[q] = __ldg(xr + q);
        float v[KC];
#pragma unroll
        for (int j = 0; j < KC; j++) {
            const float4* cbr = (const float4*)&cbS[j * DD];
            float a0 = 0.f, a1 = 0.f, a2 = 0.f, a3 = 0.f;
#pragma unroll
            for (int q = 0; q < 16; q++) {
                float4 c4 = cbr[q];
                a0 = fmaf(x4[q].x, c4.x, a0);
                a1 = fmaf(x4[q].y, c4.y, a1);
                a2 = fmaf(x4[q].z, c4.z, a2);
                a3 = fmaf(x4[q].w, c4.w, a3);
            }
            v[j] = fmaf(S2LOG2, (a0 + a1) + (a2 + a3), -sB[j]);
        }
        float m0 = v[0], m1 = v[1], m2 = v[2], m3 = v[3];
#pragma unroll
        for (int j = 4; j < KC; j += 4) {
            m0 = fmaxf(m0, v[j]);   m1 = fmaxf(m1, v[j+1]);
            m2 = fmaxf(m2, v[j+2]); m3 = fmaxf(m3, v[j+3]);
        }
        float vmax = fmaxf(fmaxf(m0, m1), fmaxf(m2, m3));
#pragma unroll
        for (int q = 0; q < 8; q++)
            *(float4*)(dst + 4 * q) =
                make_float4(v[4*q]-vmax, v[4*q+1]-vmax, v[4*q+2]-vmax, v[4*q+3]-vmax);
    } else if (i < Mtot + 8 * B) {
        int j = i - Mtot;
        int b = j >> 3;
        int end = lower_bound_dev(bidx, N, b + 1);     // one-past-last node of b
        float* dst = g_cscratch + ((size_t)end * S + (size_t)b * 8 + (j & 7)) * KC;
#pragma unroll
        for (int q = 0; q < 8; q++)
            *(float4*)(dst + 4 * q) = make_float4(NEGBIG, NEGBIG, NEGBIG, NEGBIG);
    }
}

// =============== Kernel 2: Sinkhorn passes + histogram ===============
// SMEM (floats): rows[MAX_M*36] | Gs[32] | Wp[32*32] | ctrl
#define ROWS_F   (MAX_M*CPAD)
#define SM2_FLOATS (ROWS_F + KC + NW2*KC + 8)
#define SM2_BYTES  (SM2_FLOATS*4)

extern "C" __global__ void __launch_bounds__(NTH2, 1)
sinkhorn_kernel(const int* __restrict__ bidx, float* __restrict__ out,
                int N, int S, int B) {
    extern __shared__ float sm[];
    float* smrows = sm;                       // [MAX_M][36]
    float* Gs     = sm + ROWS_F;              // shifted duals (log2 domain)
    float* Wp     = Gs + KC;                  // [32 warps][32 cols]
    int*   ctrl   = (int*)(Wp + NW2 * KC);    // [0]=lo, [1]=n, [2]=cvg

    const int tid  = threadIdx.x;
    const int lane = tid & 31;
    const int warp = tid >> 5;
    const int cidx = lane & 3;                // column group: cols 8*cidx .. +7
    const int sub  = lane >> 2;               // sample slot within 8-sample group
    const int hoff = cidx << 3;

    for (int b = blockIdx.x; b < B; b += gridDim.x) {
        if (tid == 0) {
            int lo = lower_bound_dev(bidx, N, b);
            int hi = lower_bound_dev(bidx, N, b + 1);
            ctrl[0] = lo; ctrl[1] = hi - lo; ctrl[2] = 0;
        }
        __syncthreads();

        const int lo = ctrl[0];
        const int n  = ctrl[1];
        const int m  = n * S;

        if (n == 0) {
            if (tid < KC) out[b * KC + tid] = 1.0f / KC;
            __syncthreads();
            continue;
        }

        const int ngroups = (m + 7) >> 3;
        const int pad8    = ngroups << 3;
        const bool insm   = (pad8 <= MAX_M);
        const float* grow = g_cscratch + ((size_t)lo * S + (size_t)b * 8) * KC;

        if (insm) {   // stage padded rows into smem (coalesced LDG.128)
            const float4* src = (const float4*)grow;
            int nf4 = pad8 << 3;
            for (int i = tid; i < nf4; i += NTH2) {
                int row = i >> 3, q = i & 7;
                *(float4*)&smrows[row * CPAD + (q << 2)] = __ldg(src + i);
            }
        }
        __syncthreads();

        const float log2_mK = __log2f((float)m * (1.0f / KC));
        const float inv_m   = 1.0f / (float)m;

        float G[8];
#pragma unroll
        for (int k = 0; k < 8; k++) G[k] = 0.f;
        float Gcol = 0.f;             // valid in warp 0 only

#define GROUP_MATH(P)                                                           \
        {                                                                       \
            float4 ra = LOADV((P));                                             \
            float4 rb = LOADV((P) + 4);                                         \
            float t0 = G[0] + ra.x, t1 = G[1] + ra.y;                           \
            float t2 = G[2] + ra.z, t3 = G[3] + ra.w;                           \
            float t4 = G[4] + rb.x, t5 = G[5] + rb.y;                           \
            float t6 = G[6] + rb.z, t7 = G[7] + rb.w;                           \
            float e0 = ex2f(t0), e1 = ex2f(t1), e2 = ex2f(t2), e3 = ex2f(t3);   \
            float e4 = ex2f(t4), e5 = ex2f(t5), e6 = ex2f(t6), e7 = ex2f(t7);   \
            float ssum = ((e0 + e1) + (e2 + e3)) + ((e4 + e5) + (e6 + e7));     \
            ssum += __shfl_xor_sync(0xffffffffu, ssum, 1);                      \
            ssum += __shfl_xor_sync(0xffffffffu, ssum, 2);                      \
            float inv = (ssum > 0.f) ? rcpf(ssum) : 0.f;                        \
            A[0] = fmaf(e0, inv, A[0]); A[1] = fmaf(e1, inv, A[1]);             \
            A[2] = fmaf(e2, inv, A[2]); A[3] = fmaf(e3, inv, A[3]);             \
            A[4] = fmaf(e4, inv, A[4]); A[5] = fmaf(e5, inv, A[5]);             \
            A[6] = fmaf(e6, inv, A[6]); A[7] = fmaf(e7, inv, A[7]);             \
        }

#define PASS_LOOP(ROWBASE, RSTRIDE)                                             \
    for (int pass = 0; pass <= ITERS; pass++) {                                 \
        float A[8];                                                             \
        _Pragma("unroll") for (int k = 0; k < 8; k++) A[k] = 0.f;               \
        const float* p = (ROWBASE) + (warp * 8 + sub) * (RSTRIDE) + hoff;       \
        const int step1 = NW2 * 8 * (RSTRIDE);                                  \
        int g = warp;                                                           \
        for (; g + NW2 < ngroups; g += 2 * NW2) {                               \
            GROUP_MATH(p)                                                       \
            GROUP_MATH(p + step1)                                               \
            p += 2 * step1;                                                     \
        }                                                                       \
        if (g < ngroups) GROUP_MATH(p)                                          \
        _Pragma("unroll") for (int off = 4; off <= 16; off <<= 1) {             \
            _Pragma("unroll") for (int k = 0; k < 8; k++)                       \
                A[k] += __shfl_xor_sync(0xffffffffu, A[k], off);                \
        }                                                                       \
        if (lane < 4) {                                                         \
            *(float4*)&Wp[warp * KC + hoff]     =                               \
                make_float4(A[0], A[1], A[2], A[3]);                            \
            *(float4*)&Wp[warp * KC + hoff + 4] =                               \
                make_float4(A[4], A[5], A[6], A[7]);                            \
        }                                                                       \
        __syncthreads();                                                        \
        if (warp == 0) {                                                        \
            float w = 0.f;                                                      \
            _Pragma("unroll") for (int k = 0; k < NW2; k++)                     \
                w += Wp[k * KC + lane];                                         \
            if (pass < ITERS) {                                                 \
                float dG = log2_mK - __log2f(fmaxf(w, 1e-38f));                 \
                Gcol += dG;                                                     \
                float mx = warpAllMax(Gcol);                                    \
                Gs[lane] = Gcol - mx;                                           \
                if (pass >= 10 && warpAllMax(fabsf(dG)) < TAU) ctrl[2] = 1;     \
            } else {                                                            \
                float u = w * inv_m;                                            \
                float ssum2 = warpAllSum(u) + 1e-12f;                           \
                out[b * KC + lane] = u / ssum2;                                 \
            }                                                                   \
        }                                                                       \
        __syncthreads();                                                        \
        if (pass < ITERS) {                                                     \
            float4 ga = *(const float4*)&Gs[hoff];                              \
            float4 gb = *(const float4*)&Gs[hoff + 4];                          \
            G[0] = ga.x; G[1] = ga.y; G[2] = ga.z; G[3] = ga.w;                 \
            G[4] = gb.x; G[5] = gb.y; G[6] = gb.z; G[7] = gb.w;                 \
            if (ctrl[2]) pass = ITERS - 1;                                      \
        }                                                                       \
    }

#define LOADV(pp) (*(const float4*)(pp))
        if (insm) {
            PASS_LOOP(smrows, CPAD)
        }
#undef LOADV
#define LOADV(pp) (__ldg((const float4*)(pp)))
        if (!insm) {
            PASS_LOOP(grow, KC)
        }
#undef LOADV
#undef PASS_LOOP
#undef GROUP_MATH
        __syncthreads();   // protect smrows/Gs/Wp/ctrl before next graph
    }
}

extern "C" void kernel_launch(void* const* d_in, const int* in_sizes, int n_in,
                              void* d_out, int out_size) {
    const float* X    = (const float*)d_in[0];
    const float* cb   = (const float*)d_in[1];
    const int*   bidx = (const int*)d_in[2];
    float*       out  = (float*)d_out;

    int N = in_sizes[2];
    int S = in_sizes[0] / (N * DD);
    int B = out_size / KC;
    int Mtot = N * S;

    int dev = 0, nsm = 148;
    cudaGetDevice(&dev);
    cudaDeviceGetAttribute(&nsm, cudaDevAttrMultiProcessorCount, dev);
    int grid2 = (B < nsm) ? B : nsm;

    int total1 = Mtot + 8 * B;
    phaseA_kernel<<<(total1 + 255) / 256, 256>>>(X, cb, bidx, N, S, Mtot, B);

    cudaFuncSetAttribute(sinkhorn_kernel,
                         cudaFuncAttributeMaxDynamicSharedMemorySize, SM2_BYTES);
    sinkhorn_kernel<<<grid2, NTH2, SM2_BYTES>>>(bidx, out, N, S, B);
}

// round 12
// speedup vs baseline: 1.0079x; 1.0079x over previous
#include <cuda_runtime.h>
#include <cstdint>

#define KC       32
#define DD       64
#define CPAD     36            // padded row stride (floats)
#define MAX_M    1500          // rows held in SMEM
#define ITERS    50
#define TAU      3e-4f         // early-stop threshold on max|dG| (log2 units)
#define MINPASS  8
// s = (1/eps)*log2(e) = 10 * 1.4426950408889634
#define SLOG2    14.426950408889634f
#define S2LOG2   28.853900817779268f
#define NEGBIG   -1.0e30f

#define NTH2     1024
#define NW2      32

// Scratch only for graphs too large for SMEM (rare): global layout by sample.
__device__ float g_cscratch[13100000u];

__device__ __forceinline__ float ex2f(float x) {
    float y; asm("ex2.approx.ftz.f32 %0, %1;" : "=f"(y) : "f"(x)); return y;
}
__device__ __forceinline__ float rcpf(float x) {
    float y; asm("rcp.approx.ftz.f32 %0, %1;" : "=f"(y) : "f"(x)); return y;
}
__device__ __forceinline__ float warpAllSum(float v) {
#pragma unroll
    for (int off = 16; off; off >>= 1) v += __shfl_xor_sync(0xffffffffu, v, off);
    return v;
}
__device__ __forceinline__ float warpAllMax(float v) {
#pragma unroll
    for (int off = 16; off; off >>= 1) v = fmaxf(v, __shfl_xor_sync(0xffffffffu, v, off));
    return v;
}
__device__ __forceinline__ int lower_bound_dev(const int* __restrict__ a, int n, int key) {
    int lo = 0, hi = n;
    while (lo < hi) { int mid = (lo + hi) >> 1; if (__ldg(a + mid) < key) lo = mid + 1; else hi = mid; }
    return lo;
}

// SMEM (floats): rows[MAX_M*36] | cbS[32*64] | sB[32] | Gs[32] | Wp[32*32] | ctrl
#define ROWS_F   (MAX_M*CPAD)
#define SM_FLOATS (ROWS_F + KC*DD + KC + KC + NW2*KC + 8)
#define SM_BYTES  (SM_FLOATS*4)

extern "C" __global__ void __launch_bounds__(NTH2, 1)
sinkhorn_kernel(const float* __restrict__ X, const float* __restrict__ cb,
                const int* __restrict__ bidx, float* __restrict__ out,
                int N, int S, int B) {
    extern __shared__ float sm[];
    float* smrows = sm;                       // [MAX_M][36]
    float* cbS    = sm + ROWS_F;              // [32][64]
    float* sB     = cbS + KC * DD;            // s*||cb_j||^2
    float* Gs     = sB + KC;                  // shifted duals (log2 domain)
    float* Wp     = Gs + KC;                  // [32 warps][32 cols]
    int*   ctrl   = (int*)(Wp + NW2 * KC);    // [0]=lo, [1]=n, [2]=cvg

    const int tid  = threadIdx.x;
    const int lane = tid & 31;
    const int warp = tid >> 5;
    const int cidx = lane & 3;                // column group: cols 8*cidx .. +7
    const int sub  = lane >> 2;               // sample slot within 8-sample group
    const int hoff = cidx << 3;

    // stage codebook once (persistent CTA)
    for (int i = tid; i < KC * DD; i += NTH2) cbS[i] = __ldg(cb + i);
    if (tid < KC) {
        float s = 0.f;
#pragma unroll
        for (int d = 0; d < DD; d++) { float v = __ldg(cb + tid * DD + d); s = fmaf(v, v, s); }
        sB[tid] = SLOG2 * s;
    }

    for (int b = blockIdx.x; b < B; b += gridDim.x) {
        if (tid == 0) {
            int lo = lower_bound_dev(bidx, N, b);
            int hi = lower_bound_dev(bidx, N, b + 1);
            ctrl[0] = lo; ctrl[1] = hi - lo; ctrl[2] = 0;
        }
        __syncthreads();

        const int lo = ctrl[0];
        const int n  = ctrl[1];
        const int m  = n * S;

        if (n == 0) {
            if (tid < KC) out[b * KC + tid] = 1.0f / KC;
            __syncthreads();
            continue;
        }

        const int  ngroups = (m + 7) >> 3;
        const int  pad8    = ngroups << 3;
        const bool insm    = (pad8 <= MAX_M);
        float* grow = g_cscratch + ((size_t)lo * S + (size_t)b * 8) * KC;

        // ---- Phase A (inline, register-lean): r_ij = s*(v_j - vmax_i),
        // v_j = 2s*(x.cb_j) - s*||cb_j||^2. ||x||^2 and the max(.,0) clamp
        // cancel in every softmax/LSE -> dropped. Row shift makes max_j = 0.
        // x streamed one float4 at a time against 32 accumulators (<=64 regs).
        for (int s0 = tid; s0 < pad8; s0 += NTH2) {
            float* dst = insm ? &smrows[s0 * CPAD] : (grow + (size_t)s0 * KC);
            if (s0 < m) {
                const float4* xr = (const float4*)(X + ((size_t)(lo * S + s0) << 6));
                float v[KC];
#pragma unroll
                for (int j = 0; j < KC; j++) v[j] = 0.f;
#pragma unroll
                for (int q = 0; q < 16; q++) {
                    float4 x4 = __ldg(xr + q);
#pragma unroll
                    for (int j = 0; j < KC; j++) {
                        float4 c4 = *(const float4*)&cbS[j * DD + 4 * q];
                        v[j] = fmaf(x4.x, c4.x,
                               fmaf(x4.y, c4.y,
                               fmaf(x4.z, c4.z,
                               fmaf(x4.w, c4.w, v[j]))));
                    }
                }
#pragma unroll
                for (int j = 0; j < KC; j++) v[j] = fmaf(S2LOG2, v[j], -sB[j]);
                float m0 = v[0], m1 = v[1], m2 = v[2], m3 = v[3];
#pragma unroll
                for (int j = 4; j < KC; j += 4) {
                    m0 = fmaxf(m0, v[j]);   m1 = fmaxf(m1, v[j+1]);
                    m2 = fmaxf(m2, v[j+2]); m3 = fmaxf(m3, v[j+3]);
                }
                float vmax = fmaxf(fmaxf(m0, m1), fmaxf(m2, m3));
#pragma unroll
                for (int q = 0; q < 8; q++)
                    *(float4*)(dst + 4 * q) =
                        make_float4(v[4*q]-vmax, v[4*q+1]-vmax, v[4*q+2]-vmax, v[4*q+3]-vmax);
            } else {
#pragma unroll
                for (int q = 0; q < 8; q++)
                    *(float4*)(dst + 4 * q) = make_float4(NEGBIG, NEGBIG, NEGBIG, NEGBIG);
            }
        }
        __syncthreads();

        const float log2_mK = __log2f((float)m * (1.0f / KC));
        const float inv_m   = 1.0f / (float)m;

        float G[8];
#pragma unroll
        for (int k = 0; k < 8; k++) G[k] = 0.f;
        float Gcol = 0.f;             // valid in warp 0 only

#define GROUP_MATH(P)                                                           \
        {                                                                       \
            float4 ra = LOADV((P));                                             \
            float4 rb = LOADV((P) + 4);                                         \
            float t0 = G[0] + ra.x, t1 = G[1] + ra.y;                           \
            float t2 = G[2] + ra.z, t3 = G[3] + ra.w;                           \
            float t4 = G[4] + rb.x, t5 = G[5] + rb.y;                           \
            float t6 = G[6] + rb.z, t7 = G[7] + rb.w;                           \
            float e0 = ex2f(t0), e1 = ex2f(t1), e2 = ex2f(t2), e3 = ex2f(t3);   \
            float e4 = ex2f(t4), e5 = ex2f(t5), e6 = ex2f(t6), e7 = ex2f(t7);   \
            float ssum = ((e0 + e1) + (e2 + e3)) + ((e4 + e5) + (e6 + e7));     \
            ssum += __shfl_xor_sync(0xffffffffu, ssum, 1);                      \
            ssum += __shfl_xor_sync(0xffffffffu, ssum, 2);                      \
            float inv = (ssum > 0.f) ? rcpf(ssum) : 0.f;                        \
            A[0] = fmaf(e0, inv, A[0]); A[1] = fmaf(e1, inv, A[1]);             \
            A[2] = fmaf(e2, inv, A[2]); A[3] = fmaf(e3, inv, A[3]);             \
            A[4] = fmaf(e4, inv, A[4]); A[5] = fmaf(e5, inv, A[5]);             \
            A[6] = fmaf(e6, inv, A[6]); A[7] = fmaf(e7, inv, A[7]);             \
        }

#define PASS_LOOP(ROWBASE, RSTRIDE)                                             \
    for (int pass = 0; pass <= ITERS; pass++) {                                 \
        float A[8];                                                             \
        _Pragma("unroll") for (int k = 0; k < 8; k++) A[k] = 0.f;               \
        const float* p = (ROWBASE) + (warp * 8 + sub) * (RSTRIDE) + hoff;       \
        const int step1 = NW2 * 8 * (RSTRIDE);                                  \
        int g = warp;                                                           \
        for (; g + NW2 < ngroups; g += 2 * NW2) {                               \
            GROUP_MATH(p)                                                       \
            GROUP_MATH(p + step1)                                               \
            p += 2 * step1;                                                     \
        }                                                                       \
        if (g < ngroups) GROUP_MATH(p)                                          \
        _Pragma("unroll") for (int off = 4; off <= 16; off <<= 1) {             \
            _Pragma("unroll") for (int k = 0; k < 8; k++)                       \
                A[k] += __shfl_xor_sync(0xffffffffu, A[k], off);                \
        }                                                                       \
        if (lane < 4) {                                                         \
            *(float4*)&Wp[warp * KC + hoff]     =                               \
                make_float4(A[0], A[1], A[2], A[3]);                            \
            *(float4*)&Wp[warp * KC + hoff + 4] =                               \
                make_float4(A[4], A[5], A[6], A[7]);                            \
        }                                                                       \
        __syncthreads();                                                        \
        if (warp == 0) {                                                        \
            float w = 0.f;                                                      \
            _Pragma("unroll") for (int k = 0; k < NW2; k++)                     \
                w += Wp[k * KC + lane];                                         \
            if (pass < ITERS) {                                                 \
                float dG = log2_mK - __log2f(fmaxf(w, 1e-38f));                 \
                Gcol += dG;                                                     \
                float mx = warpAllMax(Gcol);                                    \
                Gs[lane] = Gcol - mx;                                           \
                if (pass >= MINPASS && warpAllMax(fabsf(dG)) < TAU) ctrl[2] = 1;\
            } else {                                                            \
                float u = w * inv_m;                                            \
                float ssum2 = warpAllSum(u) + 1e-12f;                           \
                out[b * KC + lane] = u / ssum2;                                 \
            }                                                                   \
        }                                                                       \
        __syncthreads();                                                        \
        if (pass < ITERS) {                                                     \
            float4 ga = *(const float4*)&Gs[hoff];                              \
            float4 gb = *(const float4*)&Gs[hoff + 4];                          \
            G[0] = ga.x; G[1] = ga.y; G[2] = ga.z; G[3] = ga.w;                 \
            G[4] = gb.x; G[5] = gb.y; G[6] = gb.z; G[7] = gb.w;                 \
            if (ctrl[2]) pass = ITERS - 1;                                      \
        }                                                                       \
    }

#define LOADV(pp) (*(const float4*)(pp))
        if (insm) {
            PASS_LOOP(smrows, CPAD)
        }
#undef LOADV
#define LOADV(pp) (__ldg((const float4*)(pp)))
        if (!insm) {
            PASS_LOOP(grow, KC)
        }
#undef LOADV
#undef PASS_LOOP
#undef GROUP_MATH
        __syncthreads();   // protect smrows/Gs/Wp/ctrl before next graph
    }
}

extern "C" void kernel_launch(void* const* d_in, const int* in_sizes, int n_in,
                              void* d_out, int out_size) {
    const float* X    = (const float*)d_in[0];
    const float* cb   = (const float*)d_in[1];
    const int*   bidx = (const int*)d_in[2];
    float*       out  = (float*)d_out;

    int N = in_sizes[2];
    int S = in_sizes[0] / (N * DD);
    int B = out_size / KC;

    int dev = 0, nsm = 148;
    cudaGetDevice(&dev);
    cudaDeviceGetAttribute(&nsm, cudaDevAttrMultiProcessorCount, dev);
    int grid = (B < nsm) ? B : nsm;

    cudaFuncSetAttribute(sinkhorn_kernel,
                         cudaFuncAttributeMaxDynamicSharedMemorySize, SM_BYTES);
    sinkhorn_kernel<<<grid, NTH2, SM_BYTES>>>(X, cb, bidx, out, N, S, B);
}

// round 14
// speedup vs baseline: 1.1713x; 1.1622x over previous
#include <cuda_runtime.h>
#include <cstdint>

#define KC       32
#define DD       64
#define CPAD     36            // padded row stride (floats)
#define MAX_M    1500          // rows held in SMEM
#define ITERS    50
// s = (1/eps)*log2(e) = 10 * 1.4426950408889634
#define SLOG2    14.426950408889634f
#define S2LOG2   28.853900817779268f

#define NTH2     1024
#define NW2      32

// Scratch only for graphs too large for SMEM (rare): linear-domain R rows.
__device__ float g_cscratch[13100000u];

__device__ __forceinline__ float ex2f(float x) {
    float y; asm("ex2.approx.ftz.f32 %0, %1;" : "=f"(y) : "f"(x)); return y;
}
__device__ __forceinline__ float rcpf(float x) {
    float y; asm("rcp.approx.ftz.f32 %0, %1;" : "=f"(y) : "f"(x)); return y;
}
__device__ __forceinline__ float warpAllSum(float v) {
#pragma unroll
    for (int off = 16; off; off >>= 1) v += __shfl_xor_sync(0xffffffffu, v, off);
    return v;
}
__device__ __forceinline__ float warpAllMax(float v) {
#pragma unroll
    for (int off = 16; off; off >>= 1) v = fmaxf(v, __shfl_xor_sync(0xffffffffu, v, off));
    return v;
}
__device__ __forceinline__ int lower_bound_dev(const int* __restrict__ a, int n, int key) {
    int lo = 0, hi = n;
    while (lo < hi) { int mid = (lo + hi) >> 1; if (__ldg(a + mid) < key) lo = mid + 1; else hi = mid; }
    return lo;
}

// SMEM (floats): rows[MAX_M*36] | cbS[32*64] | sB[32] | Gs[32] | Wp[32*32] | ctrl
#define ROWS_F   (MAX_M*CPAD)
#define SM_FLOATS (ROWS_F + KC*DD + KC + KC + NW2*KC + 8)
#define SM_BYTES  (SM_FLOATS*4)

extern "C" __global__ void __launch_bounds__(NTH2, 1)
sinkhorn_kernel(const float* __restrict__ X, const float* __restrict__ cb,
                const int* __restrict__ bidx, float* __restrict__ out,
                int N, int S, int B) {
    extern __shared__ float sm[];
    float* smrows = sm;                       // [MAX_M][36]  linear-domain R
    float* cbS    = sm + ROWS_F;              // [32][64]
    float* sB     = cbS + KC * DD;            // s*||cb_j||^2
    float* Gs     = sB + KC;                  // LINEAR shifted duals g_j = 2^{G_j - maxG}
    float* Wp     = Gs + KC;                  // [32 warps][32 cols]
    int*   ctrl   = (int*)(Wp + NW2 * KC);    // [0]=lo, [1]=n

    const int tid  = threadIdx.x;
    const int lane = tid & 31;
    const int warp = tid >> 5;
    const int cidx = lane & 3;                // column group: cols 8*cidx .. +7
    const int sub  = lane >> 2;               // sample slot within 8-sample group
    const int hoff = cidx << 3;

    // stage codebook once (persistent CTA)
    for (int i = tid; i < KC * DD; i += NTH2) cbS[i] = __ldg(cb + i);
    if (tid < KC) {
        float s = 0.f;
#pragma unroll
        for (int d = 0; d < DD; d++) { float v = __ldg(cb + tid * DD + d); s = fmaf(v, v, s); }
        sB[tid] = SLOG2 * s;
    }

    for (int b = blockIdx.x; b < B; b += gridDim.x) {
        if (tid == 0) {
            int lo = lower_bound_dev(bidx, N, b);
            int hi = lower_bound_dev(bidx, N, b + 1);
            ctrl[0] = lo; ctrl[1] = hi - lo;
        }
        __syncthreads();

        const int lo = ctrl[0];
        const int n  = ctrl[1];
        const int m  = n * S;

        if (n == 0) {
            if (tid < KC) out[b * KC + tid] = 1.0f / KC;
            __syncthreads();
            continue;
        }

        const int  ngroups = (m + 7) >> 3;
        const int  pad8    = ngroups << 3;
        const bool insm    = (pad8 <= MAX_M);
        float* grow = g_cscratch + ((size_t)lo * S + (size_t)b * 8) * KC;

        // ---- Phase A: R_ij = 2^{s*(v_j - vmax_i)}, v_j = 2s*(x.cb_j) - s*||cb_j||^2.
        // ||x||^2 and the max(.,0) clamp cancel in every softmax/LSE -> dropped.
        // Row shift makes max_j R = 1. Pad rows get R = 0 (contribute nothing).
        for (int s0 = tid; s0 < pad8; s0 += NTH2) {
            float* dst = insm ? &smrows[s0 * CPAD] : (grow + (size_t)s0 * KC);
            if (s0 < m) {
                const float4* xr = (const float4*)(X + ((size_t)(lo * S + s0) << 6));
                float v[KC];
#pragma unroll
                for (int j = 0; j < KC; j++) v[j] = 0.f;
#pragma unroll
                for (int q = 0; q < 16; q++) {
                    float4 x4 = __ldg(xr + q);
#pragma unroll
                    for (int j = 0; j < KC; j++) {
                        float4 c4 = *(const float4*)&cbS[j * DD + 4 * q];
                        v[j] = fmaf(x4.x, c4.x,
                               fmaf(x4.y, c4.y,
                               fmaf(x4.z, c4.z,
                               fmaf(x4.w, c4.w, v[j]))));
                    }
                }
#pragma unroll
                for (int j = 0; j < KC; j++) v[j] = fmaf(S2LOG2, v[j], -sB[j]);
                float m0 = v[0], m1 = v[1], m2 = v[2], m3 = v[3];
#pragma unroll
                for (int j = 4; j < KC; j += 4) {
                    m0 = fmaxf(m0, v[j]);   m1 = fmaxf(m1, v[j+1]);
                    m2 = fmaxf(m2, v[j+2]); m3 = fmaxf(m3, v[j+3]);
                }
                float vmax = fmaxf(fmaxf(m0, m1), fmaxf(m2, m3));
#pragma unroll
                for (int q = 0; q < 8; q++)
                    *(float4*)(dst + 4 * q) =
                        make_float4(ex2f(v[4*q]  -vmax), ex2f(v[4*q+1]-vmax),
                                    ex2f(v[4*q+2]-vmax), ex2f(v[4*q+3]-vmax));
            } else {
#pragma unroll
                for (int q = 0; q < 8; q++)
                    *(float4*)(dst + 4 * q) = make_float4(0.f, 0.f, 0.f, 0.f);
            }
        }
        if (tid < KC) Gs[tid] = 1.0f;   // g = 2^0
        __syncthreads();

        const float log2_mK = __log2f((float)m * (1.0f / KC));
        const float inv_m   = 1.0f / (float)m;

        float gq[8];                    // linear duals for this lane's 8 columns
#pragma unroll
        for (int k = 0; k < 8; k++) gq[k] = 1.f;
        float Gcol = 0.f;               // log2 dual, valid in warp 0 only

        // ---- Linear-domain Sinkhorn: per sample, p_k = R_k * g_k;
        // rowsum via 2 bfly; u = 1/rowsum; A_k += p_k * u. NO per-element exp.
#define GROUP_MATH(P)                                                           \
        {                                                                       \
            float4 ra = LOADV((P));                                             \
            float4 rb = LOADV((P) + 4);                                         \
            float p0 = ra.x * gq[0], p1 = ra.y * gq[1];                         \
            float p2 = ra.z * gq[2], p3 = ra.w * gq[3];                         \
            float p4 = rb.x * gq[4], p5 = rb.y * gq[5];                         \
            float p6 = rb.z * gq[6], p7 = rb.w * gq[7];                         \
            float rs = ((p0 + p1) + (p2 + p3)) + ((p4 + p5) + (p6 + p7));       \
            rs += __shfl_xor_sync(0xffffffffu, rs, 1);                          \
            rs += __shfl_xor_sync(0xffffffffu, rs, 2);                          \
            float u = (rs > 0.f) ? rcpf(rs) : 0.f;                              \
            A[0] = fmaf(p0, u, A[0]); A[1] = fmaf(p1, u, A[1]);                 \
            A[2] = fmaf(p2, u, A[2]); A[3] = fmaf(p3, u, A[3]);                 \
            A[4] = fmaf(p4, u, A[4]); A[5] = fmaf(p5, u, A[5]);                 \
            A[6] = fmaf(p6, u, A[6]); A[7] = fmaf(p7, u, A[7]);                 \
        }

#define PASS_LOOP(ROWBASE, RSTRIDE)                                             \
    for (int pass = 0; pass <= ITERS; pass++) {                                 \
        float A[8];                                                             \
        _Pragma("unroll") for (int k = 0; k < 8; k++) A[k] = 0.f;               \
        const float* p = (ROWBASE) + (warp * 8 + sub) * (RSTRIDE) + hoff;       \
        const int step1 = NW2 * 8 * (RSTRIDE);                                  \
        int g = warp;                                                           \
        for (; g + NW2 < ngroups; g += 2 * NW2) {                               \
            GROUP_MATH(p)                                                       \
            GROUP_MATH(p + step1)                                               \
            p += 2 * step1;                                                     \
        }                                                                       \
        if (g < ngroups) GROUP_MATH(p)                                          \
        _Pragma("unroll") for (int off = 4; off <= 16; off <<= 1) {             \
            _Pragma("unroll") for (int k = 0; k < 8; k++)                       \
                A[k] += __shfl_xor_sync(0xffffffffu, A[k], off);                \
        }                                                                       \
        if (lane < 4) {                                                         \
            *(float4*)&Wp[warp * KC + hoff]     =                               \
                make_float4(A[0], A[1], A[2], A[3]);                            \
            *(float4*)&Wp[warp * KC + hoff + 4] =                               \
                make_float4(A[4], A[5], A[6], A[7]);                            \
        }                                                                       \
        __syncthreads();                                                        \
        if (warp == 0) {                                                        \
            float w = 0.f;                                                      \
            _Pragma("unroll") for (int k = 0; k < NW2; k++)                     \
                w += Wp[k * KC + lane];                                         \
            if (pass < ITERS) {                                                 \
                Gcol += log2_mK - __log2f(fmaxf(w, 1e-38f));                    \
                float mx = warpAllMax(Gcol);                                    \
                Gs[lane] = ex2f(Gcol - mx);     /* store LINEAR shifted g */    \
            } else {                                                            \
                float u = w * inv_m;                                            \
                float ssum2 = warpAllSum(u) + 1e-12f;                           \
                out[b * KC + lane] = u / ssum2;                                 \
            }                                                                   \
        }                                                                       \
        __syncthreads();                                                        \
        if (pass < ITERS) {                                                     \
            float4 ga = *(const float4*)&Gs[hoff];                              \
            float4 gb = *(const float4*)&Gs[hoff + 4];                          \
            gq[0] = ga.x; gq[1] = ga.y; gq[2] = ga.z; gq[3] = ga.w;             \
            gq[4] = gb.x; gq[5] = gb.y; gq[6] = gb.z; gq[7] = gb.w;             \
        }                                                                       \
    }

#define LOADV(pp) (*(const float4*)(pp))
        if (insm) {
            PASS_LOOP(smrows, CPAD)
        }
#undef LOADV
#define LOADV(pp) (__ldg((const float4*)(pp)))
        if (!insm) {
            PASS_LOOP(grow, KC)
        }
#undef LOADV
#undef PASS_LOOP
#undef GROUP_MATH
        __syncthreads();   // protect smrows/Gs/Wp/ctrl before next graph
    }
}

extern "C" void kernel_launch(void* const* d_in, const int* in_sizes, int n_in,
                              void* d_out, int out_size) {
    const float* X    = (const float*)d_in[0];
    const float* cb   = (const float*)d_in[1];
    const int*   bidx = (const int*)d_in[2];
    float*       out  = (float*)d_out;

    int N = in_sizes[2];
    int S = in_sizes[0] / (N * DD);
    int B = out_size / KC;

    int dev = 0, nsm = 148;
    cudaGetDevice(&dev);
    cudaDeviceGetAttribute(&nsm, cudaDevAttrMultiProcessorCount, dev);
    int grid = (B < nsm) ? B : nsm;

    cudaFuncSetAttribute(sinkhorn_kernel,
                         cudaFuncAttributeMaxDynamicSharedMemorySize, SM_BYTES);
    sinkhorn_kernel<<<grid, NTH2, SM_BYTES>>>(X, cb, bidx, out, N, S, B);
}